// round 5
// baseline (speedup 1.0000x reference)
#include <cuda_runtime.h>
#include <cstddef>

#define NODES  100000
#define EDGES  1600000
#define DIM    128
#define NGRAPH 128

// ---------------- scratch (static device globals; no allocation) ----------------
__device__ float g_agg[(size_t)NODES * DIM];
__device__ float g_tmp[(size_t)NODES * DIM];
__device__ float g_h1 [(size_t)NODES * DIM];
__device__ float g_h2 [(size_t)NODES * DIM];
__device__ int   g_cnt[NGRAPH];

// ---------------- packed fp32x2 helpers (Blackwell fma.rn.f32x2) ----------------
__device__ __forceinline__ void fma2(unsigned long long& d,
                                     unsigned long long a,
                                     unsigned long long b) {
    asm("fma.rn.f32x2 %0, %1, %2, %0;" : "+l"(d) : "l"(a), "l"(b));
}
__device__ __forceinline__ unsigned long long pack2(float x, float y) {
    unsigned long long r;
    asm("mov.b64 %0, {%1, %2};" : "=l"(r) : "f"(x), "f"(y));
    return r;
}
__device__ __forceinline__ float2 unpack2(unsigned long long v) {
    float2 f;
    asm("mov.b64 {%0, %1}, %2;" : "=f"(f.x), "=f"(f.y) : "l"(v));
    return f;
}

// ---------------- zero kernels (pure launches; no memset API needed) ------------
__global__ void zero_f4(float4* p, int n4) {
    int i = blockIdx.x * blockDim.x + threadIdx.x;
    if (i < n4) p[i] = make_float4(0.f, 0.f, 0.f, 0.f);
}

__global__ void zero_pool(float* out, int* cnt) {
    int i = blockIdx.x * blockDim.x + threadIdx.x;
    if (i < NGRAPH * DIM) out[i] = 0.f;
    if (i < NGRAPH) cnt[i] = 0;
}

// ---------------- edge scatter-add: agg[dst] += x[src] --------------------------
// One warp per edge; each lane moves 4 floats via one 16B vector reduction.
__global__ void scatter_add(const float* __restrict__ x,
                            const int* __restrict__ ei,
                            float* __restrict__ agg) {
    int gid  = blockIdx.x * blockDim.x + threadIdx.x;
    int e    = gid >> 5;
    if (e >= EDGES) return;
    int lane = gid & 31;
    int src  = __ldg(ei + e);
    int dst  = __ldg(ei + EDGES + e);
    const float4 v = *reinterpret_cast<const float4*>(x + (size_t)src * DIM + lane * 4);
    float* p = agg + (size_t)dst * DIM + lane * 4;
    asm volatile("red.global.add.v4.f32 [%0], {%1, %2, %3, %4};"
                 :: "l"(p), "f"(v.x), "f"(v.y), "f"(v.z), "f"(v.w)
                 : "memory");
}

// ---------------- fp32 GEMM: C[M,128] = op(A (+A2)) @ B[128,128] + bias ---------
// BM=128, BN=128(full), BK=16, 256 threads, 8x8 micro-tile, packed f32x2 FMA.
template <bool FUSE_ADD, bool RELU>
__global__ __launch_bounds__(256, 2)
void gemm128(const float* __restrict__ A, const float* __restrict__ A2,
             const float* __restrict__ B, const float* __restrict__ bias,
             float* __restrict__ C, int M) {
    __shared__ __align__(16) float As[16][128];  // As[k][m]
    __shared__ __align__(16) float Bs[16][128];  // Bs[k][n]

    const int tid = threadIdx.x;
    const int tx  = tid & 15;    // col group: cols tx*8 .. tx*8+7
    const int ty  = tid >> 4;    // row group: rows ty*8 .. ty*8+7
    const int r0  = blockIdx.x * 128;

    unsigned long long acc[8][4];
#pragma unroll
    for (int i = 0; i < 8; i++)
#pragma unroll
        for (int j = 0; j < 4; j++) acc[i][j] = 0ULL;

    for (int kb = 0; kb < 8; kb++) {
        // --- stage A tile (128 rows x 16 k), transposed into As[k][m] ---
#pragma unroll
        for (int q = 0; q < 2; q++) {
            int idx  = tid * 2 + q;        // 0..511 float4 slots
            int row  = idx >> 2;           // 0..127
            int c4   = idx & 3;            // which float4 in the 16-wide k slice
            int grow = r0 + row;
            float4 v = make_float4(0.f, 0.f, 0.f, 0.f);
            if (grow < M) {
                const float* ap = A + (size_t)grow * 128 + kb * 16 + c4 * 4;
                v = *reinterpret_cast<const float4*>(ap);
                if (FUSE_ADD) {
                    const float4 w = *reinterpret_cast<const float4*>(
                        A2 + (size_t)grow * 128 + kb * 16 + c4 * 4);
                    v.x += w.x; v.y += w.y; v.z += w.z; v.w += w.w;
                }
            }
            As[c4 * 4 + 0][row] = v.x;
            As[c4 * 4 + 1][row] = v.y;
            As[c4 * 4 + 2][row] = v.z;
            As[c4 * 4 + 3][row] = v.w;
        }
        // --- stage B tile (16 k x 128 n) ---
#pragma unroll
        for (int q = 0; q < 2; q++) {
            int idx = tid * 2 + q;
            int kk  = idx >> 5;
            int c4  = idx & 31;
            *reinterpret_cast<float4*>(&Bs[kk][c4 * 4]) =
                *reinterpret_cast<const float4*>(B + (size_t)(kb * 16 + kk) * 128 + c4 * 4);
        }
        __syncthreads();

#pragma unroll
        for (int kk = 0; kk < 16; kk++) {
            float4 a0 = *reinterpret_cast<const float4*>(&As[kk][ty * 8]);
            float4 a1 = *reinterpret_cast<const float4*>(&As[kk][ty * 8 + 4]);
            ulonglong2 p0 = *reinterpret_cast<const ulonglong2*>(&Bs[kk][tx * 8]);
            ulonglong2 p1 = *reinterpret_cast<const ulonglong2*>(&Bs[kk][tx * 8 + 4]);
            unsigned long long bb[4] = {p0.x, p0.y, p1.x, p1.y};
            float av[8] = {a0.x, a0.y, a0.z, a0.w, a1.x, a1.y, a1.z, a1.w};
#pragma unroll
            for (int i = 0; i < 8; i++) {
                unsigned long long aa = pack2(av[i], av[i]);
#pragma unroll
                for (int j = 0; j < 4; j++) fma2(acc[i][j], aa, bb[j]);
            }
        }
        __syncthreads();
    }

    // --- epilogue: + bias, optional relu, vector stores ---
    float bcol[8];
#pragma unroll
    for (int j = 0; j < 8; j++) bcol[j] = __ldg(bias + tx * 8 + j);

#pragma unroll
    for (int i = 0; i < 8; i++) {
        int grow = r0 + ty * 8 + i;
        if (grow < M) {
            float o[8];
#pragma unroll
            for (int j = 0; j < 4; j++) {
                float2 f = unpack2(acc[i][j]);
                o[2 * j + 0] = f.x + bcol[2 * j + 0];
                o[2 * j + 1] = f.y + bcol[2 * j + 1];
            }
            if (RELU) {
#pragma unroll
                for (int j = 0; j < 8; j++) o[j] = fmaxf(o[j], 0.f);
            }
            *reinterpret_cast<float4*>(C + (size_t)grow * 128 + tx * 8) =
                make_float4(o[0], o[1], o[2], o[3]);
            *reinterpret_cast<float4*>(C + (size_t)grow * 128 + tx * 8 + 4) =
                make_float4(o[4], o[5], o[6], o[7]);
        }
    }
}

// ---------------- global mean pool -----------------------------------------------
__global__ void pool_accum(const float* __restrict__ h,
                           const int* __restrict__ batch,
                           float* __restrict__ out,
                           int* __restrict__ cnt) {
    int gid  = blockIdx.x * blockDim.x + threadIdx.x;
    int node = gid >> 5;
    if (node >= NODES) return;
    int lane = gid & 31;
    int b    = __ldg(batch + node);
    const float4 v = *reinterpret_cast<const float4*>(h + (size_t)node * DIM + lane * 4);
    float* p = out + (size_t)b * DIM + lane * 4;
    asm volatile("red.global.add.v4.f32 [%0], {%1, %2, %3, %4};"
                 :: "l"(p), "f"(v.x), "f"(v.y), "f"(v.z), "f"(v.w)
                 : "memory");
    if (lane == 0) atomicAdd(cnt + b, 1);
}

__global__ void pool_div(float* out, const int* __restrict__ cnt) {
    int i = blockIdx.x * blockDim.x + threadIdx.x;
    if (i < NGRAPH * DIM) {
        int c = cnt[i >> 7];
        out[i] = out[i] / (float)(c > 0 ? c : 1);
    }
}

// ---------------- launch ----------------------------------------------------------
extern "C" void kernel_launch(void* const* d_in, const int* in_sizes, int n_in,
                              void* d_out, int out_size) {
    const float* x     = (const float*)d_in[0];
    const int*   ei    = (const int*)d_in[1];
    const int*   batch = (const int*)d_in[2];
    float*       out   = (float*)d_out;

    float *agg, *tmp, *h1, *h2;
    int* cnt;
    cudaGetSymbolAddress((void**)&agg, g_agg);
    cudaGetSymbolAddress((void**)&tmp, g_tmp);
    cudaGetSymbolAddress((void**)&h1,  g_h1);
    cudaGetSymbolAddress((void**)&h2,  g_h2);
    cudaGetSymbolAddress((void**)&cnt, g_cnt);

    const int ZB = (NODES * DIM / 4 + 255) / 256;   // zero agg
    const int SB = (EDGES * 32 + 255) / 256;        // scatter: warp per edge
    const int GB = (NODES + 127) / 128;             // gemm row tiles
    const int PB = (NODES * 32 + 255) / 256;        // pool: warp per node

    const float* cur = x;
    float* dst_buf[3] = {h1, h2, h1};

    for (int l = 0; l < 3; l++) {
        const float* W1 = (const float*)d_in[3 + 4 * l];
        const float* B1 = (const float*)d_in[4 + 4 * l];
        const float* W2 = (const float*)d_in[5 + 4 * l];
        const float* B2 = (const float*)d_in[6 + 4 * l];

        zero_f4<<<ZB, 256>>>((float4*)agg, NODES * DIM / 4);
        scatter_add<<<SB, 256>>>(cur, ei, agg);
        gemm128<true,  true ><<<GB, 256>>>(cur, agg, W1, B1, tmp, NODES);
        gemm128<false, false><<<GB, 256>>>(tmp, nullptr, W2, B2, dst_buf[l], NODES);
        cur = dst_buf[l];
    }

    zero_pool<<<64, 256>>>(out, cnt);
    pool_accum<<<PB, 256>>>(cur, batch, out, cnt);
    pool_div<<<64, 256>>>(out, cnt);
}

// round 6
// speedup vs baseline: 1.0022x; 1.0022x over previous
#include <cuda_runtime.h>
#include <cstddef>

#define NODES  100000
#define EDGES  1600000
#define DIM    128
#define NGRAPH 128

// ---------------- scratch (static device globals; no allocation) ----------------
__device__ float g_agg[(size_t)NODES * DIM];
__device__ float g_tmp[(size_t)NODES * DIM];
__device__ float g_h1 [(size_t)NODES * DIM];
__device__ float g_h2 [(size_t)NODES * DIM];
__device__ int   g_cnt[NGRAPH];

// ---------------- packed fp32x2 helpers (Blackwell fma.rn.f32x2) ----------------
__device__ __forceinline__ void fma2(unsigned long long& d,
                                     unsigned long long a,
                                     unsigned long long b) {
    asm("fma.rn.f32x2 %0, %1, %2, %0;" : "+l"(d) : "l"(a), "l"(b));
}
__device__ __forceinline__ unsigned long long pack2(float x, float y) {
    unsigned long long r;
    asm("mov.b64 %0, {%1, %2};" : "=l"(r) : "f"(x), "f"(y));
    return r;
}
__device__ __forceinline__ float2 unpack2(unsigned long long v) {
    float2 f;
    asm("mov.b64 {%0, %1}, %2;" : "=f"(f.x), "=f"(f.y) : "l"(v));
    return f;
}

// ---------------- zero kernels (pure launches; no memset API needed) ------------
__global__ void zero_f4(float4* p, int n4) {
    int i = blockIdx.x * blockDim.x + threadIdx.x;
    if (i < n4) p[i] = make_float4(0.f, 0.f, 0.f, 0.f);
}

__global__ void zero_pool(float* out, int* cnt) {
    int i = blockIdx.x * blockDim.x + threadIdx.x;
    if (i < NGRAPH * DIM) out[i] = 0.f;
    if (i < NGRAPH) cnt[i] = 0;
}

// ---------------- edge scatter-add: agg[dst] += x[src] --------------------------
// One warp per edge; each lane moves 4 floats via one 16B vector reduction.
__global__ void scatter_add(const float* __restrict__ x,
                            const int* __restrict__ ei,
                            float* __restrict__ agg) {
    int gid  = blockIdx.x * blockDim.x + threadIdx.x;
    int e    = gid >> 5;
    if (e >= EDGES) return;
    int lane = gid & 31;
    int src  = __ldg(ei + e);
    int dst  = __ldg(ei + EDGES + e);
    const float4 v = *reinterpret_cast<const float4*>(x + (size_t)src * DIM + lane * 4);
    float* p = agg + (size_t)dst * DIM + lane * 4;
    asm volatile("red.global.add.v4.f32 [%0], {%1, %2, %3, %4};"
                 :: "l"(p), "f"(v.x), "f"(v.y), "f"(v.z), "f"(v.w)
                 : "memory");
}

// ---------------- fp32 GEMM: C[M,128] = op(A (+A2)) @ B[128,128] + bias ---------
// BM=128, BN=128(full), BK=16, 256 threads, 8x8 micro-tile, packed f32x2 FMA.
template <bool FUSE_ADD, bool RELU>
__global__ __launch_bounds__(256, 2)
void gemm128(const float* __restrict__ A, const float* __restrict__ A2,
             const float* __restrict__ B, const float* __restrict__ bias,
             float* __restrict__ C, int M) {
    __shared__ __align__(16) float As[16][128];  // As[k][m]
    __shared__ __align__(16) float Bs[16][128];  // Bs[k][n]

    const int tid = threadIdx.x;
    const int tx  = tid & 15;    // col group: cols tx*8 .. tx*8+7
    const int ty  = tid >> 4;    // row group: rows ty*8 .. ty*8+7
    const int r0  = blockIdx.x * 128;

    unsigned long long acc[8][4];
#pragma unroll
    for (int i = 0; i < 8; i++)
#pragma unroll
        for (int j = 0; j < 4; j++) acc[i][j] = 0ULL;

    for (int kb = 0; kb < 8; kb++) {
        // --- stage A tile (128 rows x 16 k), transposed into As[k][m] ---
#pragma unroll
        for (int q = 0; q < 2; q++) {
            int idx  = tid * 2 + q;        // 0..511 float4 slots
            int row  = idx >> 2;           // 0..127
            int c4   = idx & 3;            // which float4 in the 16-wide k slice
            int grow = r0 + row;
            float4 v = make_float4(0.f, 0.f, 0.f, 0.f);
            if (grow < M) {
                const float* ap = A + (size_t)grow * 128 + kb * 16 + c4 * 4;
                v = *reinterpret_cast<const float4*>(ap);
                if (FUSE_ADD) {
                    const float4 w = *reinterpret_cast<const float4*>(
                        A2 + (size_t)grow * 128 + kb * 16 + c4 * 4);
                    v.x += w.x; v.y += w.y; v.z += w.z; v.w += w.w;
                }
            }
            As[c4 * 4 + 0][row] = v.x;
            As[c4 * 4 + 1][row] = v.y;
            As[c4 * 4 + 2][row] = v.z;
            As[c4 * 4 + 3][row] = v.w;
        }
        // --- stage B tile (16 k x 128 n) ---
#pragma unroll
        for (int q = 0; q < 2; q++) {
            int idx = tid * 2 + q;
            int kk  = idx >> 5;
            int c4  = idx & 31;
            *reinterpret_cast<float4*>(&Bs[kk][c4 * 4]) =
                *reinterpret_cast<const float4*>(B + (size_t)(kb * 16 + kk) * 128 + c4 * 4);
        }
        __syncthreads();

#pragma unroll
        for (int kk = 0; kk < 16; kk++) {
            float4 a0 = *reinterpret_cast<const float4*>(&As[kk][ty * 8]);
            float4 a1 = *reinterpret_cast<const float4*>(&As[kk][ty * 8 + 4]);
            ulonglong2 p0 = *reinterpret_cast<const ulonglong2*>(&Bs[kk][tx * 8]);
            ulonglong2 p1 = *reinterpret_cast<const ulonglong2*>(&Bs[kk][tx * 8 + 4]);
            unsigned long long bb[4] = {p0.x, p0.y, p1.x, p1.y};
            float av[8] = {a0.x, a0.y, a0.z, a0.w, a1.x, a1.y, a1.z, a1.w};
#pragma unroll
            for (int i = 0; i < 8; i++) {
                unsigned long long aa = pack2(av[i], av[i]);
#pragma unroll
                for (int j = 0; j < 4; j++) fma2(acc[i][j], aa, bb[j]);
            }
        }
        __syncthreads();
    }

    // --- epilogue: + bias, optional relu, vector stores ---
    float bcol[8];
#pragma unroll
    for (int j = 0; j < 8; j++) bcol[j] = __ldg(bias + tx * 8 + j);

#pragma unroll
    for (int i = 0; i < 8; i++) {
        int grow = r0 + ty * 8 + i;
        if (grow < M) {
            float o[8];
#pragma unroll
            for (int j = 0; j < 4; j++) {
                float2 f = unpack2(acc[i][j]);
                o[2 * j + 0] = f.x + bcol[2 * j + 0];
                o[2 * j + 1] = f.y + bcol[2 * j + 1];
            }
            if (RELU) {
#pragma unroll
                for (int j = 0; j < 8; j++) o[j] = fmaxf(o[j], 0.f);
            }
            *reinterpret_cast<float4*>(C + (size_t)grow * 128 + tx * 8) =
                make_float4(o[0], o[1], o[2], o[3]);
            *reinterpret_cast<float4*>(C + (size_t)grow * 128 + tx * 8 + 4) =
                make_float4(o[4], o[5], o[6], o[7]);
        }
    }
}

// ---------------- global mean pool -----------------------------------------------
__global__ void pool_accum(const float* __restrict__ h,
                           const int* __restrict__ batch,
                           float* __restrict__ out,
                           int* __restrict__ cnt) {
    int gid  = blockIdx.x * blockDim.x + threadIdx.x;
    int node = gid >> 5;
    if (node >= NODES) return;
    int lane = gid & 31;
    int b    = __ldg(batch + node);
    const float4 v = *reinterpret_cast<const float4*>(h + (size_t)node * DIM + lane * 4);
    float* p = out + (size_t)b * DIM + lane * 4;
    asm volatile("red.global.add.v4.f32 [%0], {%1, %2, %3, %4};"
                 :: "l"(p), "f"(v.x), "f"(v.y), "f"(v.z), "f"(v.w)
                 : "memory");
    if (lane == 0) atomicAdd(cnt + b, 1);
}

__global__ void pool_div(float* out, const int* __restrict__ cnt) {
    int i = blockIdx.x * blockDim.x + threadIdx.x;
    if (i < NGRAPH * DIM) {
        int c = cnt[i >> 7];
        out[i] = out[i] / (float)(c > 0 ? c : 1);
    }
}

// ---------------- launch ----------------------------------------------------------
extern "C" void kernel_launch(void* const* d_in, const int* in_sizes, int n_in,
                              void* d_out, int out_size) {
    const float* x     = (const float*)d_in[0];
    const int*   ei    = (const int*)d_in[1];
    const int*   batch = (const int*)d_in[2];
    float*       out   = (float*)d_out;

    float *agg, *tmp, *h1, *h2;
    int* cnt;
    cudaGetSymbolAddress((void**)&agg, g_agg);
    cudaGetSymbolAddress((void**)&tmp, g_tmp);
    cudaGetSymbolAddress((void**)&h1,  g_h1);
    cudaGetSymbolAddress((void**)&h2,  g_h2);
    cudaGetSymbolAddress((void**)&cnt, g_cnt);

    const int ZB = (NODES * DIM / 4 + 255) / 256;   // zero agg
    const int SB = (EDGES * 32 + 255) / 256;        // scatter: warp per edge
    const int GB = (NODES + 127) / 128;             // gemm row tiles
    const int PB = (NODES * 32 + 255) / 256;        // pool: warp per node

    const float* cur = x;
    float* dst_buf[3] = {h1, h2, h1};

    for (int l = 0; l < 3; l++) {
        const float* W1 = (const float*)d_in[3 + 4 * l];
        const float* B1 = (const float*)d_in[4 + 4 * l];
        const float* W2 = (const float*)d_in[5 + 4 * l];
        const float* B2 = (const float*)d_in[6 + 4 * l];

        zero_f4<<<ZB, 256>>>((float4*)agg, NODES * DIM / 4);
        scatter_add<<<SB, 256>>>(cur, ei, agg);
        gemm128<true,  true ><<<GB, 256>>>(cur, agg, W1, B1, tmp, NODES);
        gemm128<false, false><<<GB, 256>>>(tmp, nullptr, W2, B2, dst_buf[l], NODES);
        cur = dst_buf[l];
    }

    zero_pool<<<64, 256>>>(out, cnt);
    pool_accum<<<PB, 256>>>(cur, batch, out, cnt);
    pool_div<<<64, 256>>>(out, cnt);
}

// round 8
// speedup vs baseline: 1.4807x; 1.4775x over previous
#include <cuda_runtime.h>
#include <cstddef>

#define NODES  100000
#define EDGES  1600000
#define DIM    128
#define NGRAPH 128
#define NBLK   391          // ceil(NODES/256)

// ---------------- scratch (static device globals; no allocation) ----------------
__device__ float g_agg[(size_t)NODES * DIM];   // MLP input  (x + sum_neighbors)
__device__ float g_tmp[(size_t)NODES * DIM];
__device__ float g_h1 [(size_t)NODES * DIM];
__device__ float g_h2 [(size_t)NODES * DIM];
__device__ int   g_cnt[NGRAPH];
// counting-sort scratch
__device__ int g_deg [NODES];
__device__ int g_off [NODES];
__device__ int g_cur [NODES];
__device__ int g_bsum[NBLK + 1];
__device__ int g_ssrc[EDGES];

// ---------------- packed fp32x2 helpers (Blackwell fma.rn.f32x2) ----------------
__device__ __forceinline__ void fma2(unsigned long long& d,
                                     unsigned long long a,
                                     unsigned long long b) {
    asm("fma.rn.f32x2 %0, %1, %2, %0;" : "+l"(d) : "l"(a), "l"(b));
}
__device__ __forceinline__ unsigned long long pack2(float x, float y) {
    unsigned long long r;
    asm("mov.b64 %0, {%1, %2};" : "=l"(r) : "f"(x), "f"(y));
    return r;
}
__device__ __forceinline__ float2 unpack2(unsigned long long v) {
    float2 f;
    asm("mov.b64 {%0, %1}, %2;" : "=f"(f.x), "=f"(f.y) : "l"(v));
    return f;
}

// =================== counting sort of edges by dst ==============================
__global__ void deg_zero(int* deg) {
    int i = blockIdx.x * blockDim.x + threadIdx.x;
    if (i < NODES) deg[i] = 0;
}
__global__ void hist_dst(const int* __restrict__ ei, int* __restrict__ deg) {
    int e = blockIdx.x * blockDim.x + threadIdx.x;
    if (e < EDGES) atomicAdd(deg + __ldg(ei + EDGES + e), 1);
}
// per-block exclusive scan; block totals to bsum
__global__ void scan1(const int* __restrict__ deg, int* __restrict__ off,
                      int* __restrict__ bsum) {
    __shared__ int s[256];
    int i = blockIdx.x * 256 + threadIdx.x;
    int v = (i < NODES) ? deg[i] : 0;
    s[threadIdx.x] = v;
    __syncthreads();
#pragma unroll
    for (int d = 1; d < 256; d <<= 1) {
        int t = (threadIdx.x >= d) ? s[threadIdx.x - d] : 0;
        __syncthreads();
        s[threadIdx.x] += t;
        __syncthreads();
    }
    if (i < NODES) off[i] = s[threadIdx.x] - v;         // exclusive within block
    if (threadIdx.x == 255) bsum[blockIdx.x] = s[255];  // block total
}
// exclusive scan of block totals (single block)
__global__ void scan2(int* __restrict__ bsum) {
    __shared__ int s[512];
    int v = (threadIdx.x < NBLK) ? bsum[threadIdx.x] : 0;
    s[threadIdx.x] = v;
    __syncthreads();
#pragma unroll
    for (int d = 1; d < 512; d <<= 1) {
        int t = (threadIdx.x >= d) ? s[threadIdx.x - d] : 0;
        __syncthreads();
        s[threadIdx.x] += t;
        __syncthreads();
    }
    if (threadIdx.x < NBLK) bsum[threadIdx.x] = s[threadIdx.x] - v;
}
__global__ void scan3(int* __restrict__ off, const int* __restrict__ bsum,
                      int* __restrict__ cur) {
    int i = blockIdx.x * 256 + threadIdx.x;
    if (i < NODES) {
        int o = off[i] + bsum[blockIdx.x];
        off[i] = o;
        cur[i] = o;
    }
}
__global__ void fill_sorted(const int* __restrict__ ei, int* __restrict__ cur,
                            int* __restrict__ ssrc) {
    int e = blockIdx.x * blockDim.x + threadIdx.x;
    if (e < EDGES) {
        int d = __ldg(ei + EDGES + e);
        int p = atomicAdd(cur + d, 1);
        ssrc[p] = __ldg(ei + e);
    }
}

// =================== gather aggregation: out[i] = x[i] + sum_j x[src_j] =========
// One warp per node; 4-edge batches for MLP; register accumulation; plain stores.
__global__ __launch_bounds__(256)
void agg_gather(const float* __restrict__ x,
                const int* __restrict__ ssrc,
                const int* __restrict__ off,
                const int* __restrict__ deg,
                float* __restrict__ out) {
    int gid  = blockIdx.x * blockDim.x + threadIdx.x;
    int node = gid >> 5;
    if (node >= NODES) return;
    int lane = gid & 31;

    int s = __ldg(off + node);
    int n = __ldg(deg + node);
    const float* xl = x + lane * 4;

    float4 acc = *reinterpret_cast<const float4*>(x + (size_t)node * DIM + lane * 4);

    int i = 0;
    for (; i + 4 <= n; i += 4) {
        int s0 = __ldg(ssrc + s + i + 0);
        int s1 = __ldg(ssrc + s + i + 1);
        int s2 = __ldg(ssrc + s + i + 2);
        int s3 = __ldg(ssrc + s + i + 3);
        float4 v0 = *reinterpret_cast<const float4*>(xl + (size_t)s0 * DIM);
        float4 v1 = *reinterpret_cast<const float4*>(xl + (size_t)s1 * DIM);
        float4 v2 = *reinterpret_cast<const float4*>(xl + (size_t)s2 * DIM);
        float4 v3 = *reinterpret_cast<const float4*>(xl + (size_t)s3 * DIM);
        v0.x += v1.x; v0.y += v1.y; v0.z += v1.z; v0.w += v1.w;
        v2.x += v3.x; v2.y += v3.y; v2.z += v3.z; v2.w += v3.w;
        acc.x += v0.x + v2.x; acc.y += v0.y + v2.y;
        acc.z += v0.z + v2.z; acc.w += v0.w + v2.w;
    }
    for (; i < n; i++) {
        int s0 = __ldg(ssrc + s + i);
        float4 v = *reinterpret_cast<const float4*>(xl + (size_t)s0 * DIM);
        acc.x += v.x; acc.y += v.y; acc.z += v.z; acc.w += v.w;
    }
    *reinterpret_cast<float4*>(out + (size_t)node * DIM + lane * 4) = acc;
}

// =================== fp32 GEMM: C[M,128] = A @ B[128,128] + bias ================
// Double-buffered smem pipeline, BK=16, 256 threads, 8x8 micro-tile, FFMA2.
template <bool RELU>
__global__ __launch_bounds__(256, 2)
void gemm128(const float* __restrict__ A, const float* __restrict__ B,
             const float* __restrict__ bias, float* __restrict__ C, int M) {
    __shared__ __align__(16) float As[2][16][128];  // As[buf][k][m]
    __shared__ __align__(16) float Bs[2][16][128];  // Bs[buf][k][n]

    const int tid = threadIdx.x;
    const int tx  = tid & 15;
    const int ty  = tid >> 4;
    const int r0  = blockIdx.x * 128;

    // staging slot geometry (2 float4 slots per thread, per operand)
    const int idx0 = tid * 2, idx1 = tid * 2 + 1;
    const int rowA0 = idx0 >> 2, c40 = idx0 & 3;
    const int rowA1 = idx1 >> 2, c41 = idx1 & 3;
    const int kkB0 = idx0 >> 5, c4b0 = idx0 & 31;
    const int kkB1 = idx1 >> 5, c4b1 = idx1 & 31;
    const bool okA0 = (r0 + rowA0) < M;
    const bool okA1 = (r0 + rowA1) < M;

    float4 ra0, ra1, rb0, rb1;

#define LOADG(kb)                                                                  \
    do {                                                                           \
        ra0 = okA0 ? *reinterpret_cast<const float4*>(                             \
                         A + (size_t)(r0 + rowA0) * 128 + (kb) * 16 + c40 * 4)     \
                   : make_float4(0.f, 0.f, 0.f, 0.f);                              \
        ra1 = okA1 ? *reinterpret_cast<const float4*>(                             \
                         A + (size_t)(r0 + rowA1) * 128 + (kb) * 16 + c41 * 4)     \
                   : make_float4(0.f, 0.f, 0.f, 0.f);                              \
        rb0 = *reinterpret_cast<const float4*>(                                    \
            B + (size_t)((kb) * 16 + kkB0) * 128 + c4b0 * 4);                      \
        rb1 = *reinterpret_cast<const float4*>(                                    \
            B + (size_t)((kb) * 16 + kkB1) * 128 + c4b1 * 4);                      \
    } while (0)

#define STORES(buf)                                                                \
    do {                                                                           \
        As[buf][c40 * 4 + 0][rowA0] = ra0.x;                                       \
        As[buf][c40 * 4 + 1][rowA0] = ra0.y;                                       \
        As[buf][c40 * 4 + 2][rowA0] = ra0.z;                                       \
        As[buf][c40 * 4 + 3][rowA0] = ra0.w;                                       \
        As[buf][c41 * 4 + 0][rowA1] = ra1.x;                                       \
        As[buf][c41 * 4 + 1][rowA1] = ra1.y;                                       \
        As[buf][c41 * 4 + 2][rowA1] = ra1.z;                                       \
        As[buf][c41 * 4 + 3][rowA1] = ra1.w;                                       \
        *reinterpret_cast<float4*>(&Bs[buf][kkB0][c4b0 * 4]) = rb0;                \
        *reinterpret_cast<float4*>(&Bs[buf][kkB1][c4b1 * 4]) = rb1;                \
    } while (0)

    unsigned long long acc[8][4];
#pragma unroll
    for (int i = 0; i < 8; i++)
#pragma unroll
        for (int j = 0; j < 4; j++) acc[i][j] = 0ULL;

    LOADG(0);
    STORES(0);
    __syncthreads();

    for (int kb = 0; kb < 8; kb++) {
        const int buf = kb & 1;
        if (kb < 7) LOADG(kb + 1);  // in flight during compute

#pragma unroll
        for (int kk = 0; kk < 16; kk++) {
            float4 a0 = *reinterpret_cast<const float4*>(&As[buf][kk][ty * 8]);
            float4 a1 = *reinterpret_cast<const float4*>(&As[buf][kk][ty * 8 + 4]);
            ulonglong2 p0 = *reinterpret_cast<const ulonglong2*>(&Bs[buf][kk][tx * 8]);
            ulonglong2 p1 = *reinterpret_cast<const ulonglong2*>(&Bs[buf][kk][tx * 8 + 4]);
            unsigned long long bb[4] = {p0.x, p0.y, p1.x, p1.y};
            float av[8] = {a0.x, a0.y, a0.z, a0.w, a1.x, a1.y, a1.z, a1.w};
#pragma unroll
            for (int i = 0; i < 8; i++) {
                unsigned long long aa = pack2(av[i], av[i]);
#pragma unroll
                for (int j = 0; j < 4; j++) fma2(acc[i][j], aa, bb[j]);
            }
        }
        if (kb < 7) STORES((kb + 1) & 1);  // other buffer: safe, consumers synced last iter
        __syncthreads();
    }
#undef LOADG
#undef STORES

    float bcol[8];
#pragma unroll
    for (int j = 0; j < 8; j++) bcol[j] = __ldg(bias + tx * 8 + j);

#pragma unroll
    for (int i = 0; i < 8; i++) {
        int grow = r0 + ty * 8 + i;
        if (grow < M) {
            float o[8];
#pragma unroll
            for (int j = 0; j < 4; j++) {
                float2 f = unpack2(acc[i][j]);
                o[2 * j + 0] = f.x + bcol[2 * j + 0];
                o[2 * j + 1] = f.y + bcol[2 * j + 1];
            }
            if (RELU) {
#pragma unroll
                for (int j = 0; j < 8; j++) o[j] = fmaxf(o[j], 0.f);
            }
            *reinterpret_cast<float4*>(C + (size_t)grow * 128 + tx * 8) =
                make_float4(o[0], o[1], o[2], o[3]);
            *reinterpret_cast<float4*>(C + (size_t)grow * 128 + tx * 8 + 4) =
                make_float4(o[4], o[5], o[6], o[7]);
        }
    }
}

// =================== global mean pool ===========================================
__global__ void zero_pool(float* out, int* cnt) {
    int i = blockIdx.x * blockDim.x + threadIdx.x;
    if (i < NGRAPH * DIM) out[i] = 0.f;
    if (i < NGRAPH) cnt[i] = 0;
}
__global__ void pool_accum(const float* __restrict__ h,
                           const int* __restrict__ batch,
                           float* __restrict__ out,
                           int* __restrict__ cnt) {
    int gid  = blockIdx.x * blockDim.x + threadIdx.x;
    int node = gid >> 5;
    if (node >= NODES) return;
    int lane = gid & 31;
    int b    = __ldg(batch + node);
    const float4 v = *reinterpret_cast<const float4*>(h + (size_t)node * DIM + lane * 4);
    float* p = out + (size_t)b * DIM + lane * 4;
    asm volatile("red.global.add.v4.f32 [%0], {%1, %2, %3, %4};"
                 :: "l"(p), "f"(v.x), "f"(v.y), "f"(v.z), "f"(v.w)
                 : "memory");
    if (lane == 0) atomicAdd(cnt + b, 1);
}
__global__ void pool_div(float* out, const int* __restrict__ cnt) {
    int i = blockIdx.x * blockDim.x + threadIdx.x;
    if (i < NGRAPH * DIM) {
        int c = cnt[i >> 7];
        out[i] = out[i] / (float)(c > 0 ? c : 1);
    }
}

// =================== launch =====================================================
extern "C" void kernel_launch(void* const* d_in, const int* in_sizes, int n_in,
                              void* d_out, int out_size) {
    const float* x     = (const float*)d_in[0];
    const int*   ei    = (const int*)d_in[1];
    const int*   batch = (const int*)d_in[2];
    float*       out   = (float*)d_out;

    float *agg, *tmp, *h1, *h2;
    int *cnt, *deg, *off, *cur, *bsum, *ssrc;
    cudaGetSymbolAddress((void**)&agg,  g_agg);
    cudaGetSymbolAddress((void**)&tmp,  g_tmp);
    cudaGetSymbolAddress((void**)&h1,   g_h1);
    cudaGetSymbolAddress((void**)&h2,   g_h2);
    cudaGetSymbolAddress((void**)&cnt,  g_cnt);
    cudaGetSymbolAddress((void**)&deg,  g_deg);
    cudaGetSymbolAddress((void**)&off,  g_off);
    cudaGetSymbolAddress((void**)&cur,  g_cur);
    cudaGetSymbolAddress((void**)&bsum, g_bsum);
    cudaGetSymbolAddress((void**)&ssrc, g_ssrc);

    const int EB = (EDGES + 255) / 256;         // per-edge kernels
    const int GB = (NODES + 127) / 128;         // gemm row tiles
    const int WB = (NODES * 32 + 255) / 256;    // warp-per-node kernels

    // ---- counting sort of edges by dst (once; reused by all 3 layers) ----
    deg_zero   <<<NBLK, 256>>>(deg);
    hist_dst   <<<EB, 256>>>(ei, deg);
    scan1      <<<NBLK, 256>>>(deg, off, bsum);
    scan2      <<<1, 512>>>(bsum);
    scan3      <<<NBLK, 256>>>(off, bsum, cur);
    fill_sorted<<<EB, 256>>>(ei, cur, ssrc);

    const float* curh = x;
    float* dst_buf[3] = {h1, h2, h1};

    for (int l = 0; l < 3; l++) {
        const float* W1 = (const float*)d_in[3 + 4 * l];
        const float* B1 = (const float*)d_in[4 + 4 * l];
        const float* W2 = (const float*)d_in[5 + 4 * l];
        const float* B2 = (const float*)d_in[6 + 4 * l];

        agg_gather<<<WB, 256>>>(curh, ssrc, off, deg, agg);
        gemm128<true ><<<GB, 256>>>(agg, W1, B1, tmp, NODES);
        gemm128<false><<<GB, 256>>>(tmp, W2, B2, dst_buf[l], NODES);
        curh = dst_buf[l];
    }

    zero_pool <<<64, 256>>>(out, cnt);
    pool_accum<<<WB, 256>>>(curh, batch, out, cnt);
    pool_div  <<<64, 256>>>(out, cnt);
}